// round 1
// baseline (speedup 1.0000x reference)
#include <cuda_runtime.h>

#define SS 256
#define CC 128
#define HH 4
#define DD 32
#define TT (SS*SS)   // 65536 tokens

// Scratch (device globals; no allocations allowed)
__device__ float g_Q[(size_t)SS*HH*SS*DD];   // [s][h][q][d]
__device__ float g_K[(size_t)SS*HH*SS*DD];   // [s][h][k][d]
__device__ float g_V[(size_t)SS*HH*SS*DD];   // [s][h][k][d]
__device__ float g_G[(size_t)TT*CC];         // [t][n] sigmoid gate
__device__ float g_O[(size_t)TT*CC];         // [t][n] gated attention output

// MODE: 0=Q (scale 1/sqrt(32), head layout), 1=K (head), 2=V (head),
//       3=G (bias+sigmoid, token layout), 4=final (bias, token layout -> d_out)
template<int MODE>
__global__ void __launch_bounds__(256) gemm128(const float* __restrict__ X,
                                               const float* __restrict__ W,
                                               const float* __restrict__ bias,
                                               float* __restrict__ outp)
{
    __shared__ float Xs[32][128];
    __shared__ float Ws[32][128];

    const float* Xp = (MODE == 4) ? (const float*)g_O : X;

    const int tid = threadIdx.x;
    const int tx = tid & 15;
    const int ty = tid >> 4;
    const int m0 = blockIdx.x * 128;

    float acc[8][8];
#pragma unroll
    for (int i = 0; i < 8; i++)
#pragma unroll
        for (int j = 0; j < 8; j++) acc[i][j] = 0.f;

    for (int k0 = 0; k0 < 128; k0 += 32) {
#pragma unroll
        for (int r = 0; r < 4; r++) {
            int idx = tid + r * 256;          // 0..1023
            int row = idx >> 3;               // 0..127
            int c4  = (idx & 7) * 4;          // 0,4,...,28
            float4 xv = *(const float4*)(Xp + (size_t)(m0 + row) * CC + k0 + c4);
            Xs[c4+0][row] = xv.x; Xs[c4+1][row] = xv.y;
            Xs[c4+2][row] = xv.z; Xs[c4+3][row] = xv.w;
            float4 wv = *(const float4*)(W + (size_t)row * CC + k0 + c4);
            Ws[c4+0][row] = wv.x; Ws[c4+1][row] = wv.y;
            Ws[c4+2][row] = wv.z; Ws[c4+3][row] = wv.w;
        }
        __syncthreads();
#pragma unroll
        for (int kk = 0; kk < 32; kk++) {
            float a[8], b[8];
#pragma unroll
            for (int i = 0; i < 8; i++) a[i] = Xs[kk][ty*8 + i];
#pragma unroll
            for (int j = 0; j < 8; j++) b[j] = Ws[kk][tx*8 + j];
#pragma unroll
            for (int i = 0; i < 8; i++)
#pragma unroll
                for (int j = 0; j < 8; j++)
                    acc[i][j] = fmaf(a[i], b[j], acc[i][j]);
        }
        __syncthreads();
    }

    if (MODE <= 2) {
        float* dst = (MODE == 0) ? g_Q : (MODE == 1 ? g_K : g_V);
        const float sc = (MODE == 0) ? 0.17677669529663687f : 1.0f;
        const int n0 = tx * 8;
        const int h = n0 >> 5;
        const int d = n0 & 31;
#pragma unroll
        for (int i = 0; i < 8; i++) {
            int t  = m0 + ty*8 + i;
            int si = t >> 8;
            int j  = t & 255;
            float* p = dst + ((((size_t)si*HH + h)*SS + j)*DD + d);
            *(float4*)(p)   = make_float4(acc[i][0]*sc, acc[i][1]*sc, acc[i][2]*sc, acc[i][3]*sc);
            *(float4*)(p+4) = make_float4(acc[i][4]*sc, acc[i][5]*sc, acc[i][6]*sc, acc[i][7]*sc);
        }
    } else {
        float* dst = (MODE == 3) ? g_G : outp;
        const int n0 = tx * 8;
        float bb[8];
#pragma unroll
        for (int j = 0; j < 8; j++) bb[j] = bias[n0 + j];
#pragma unroll
        for (int i = 0; i < 8; i++) {
            int t = m0 + ty*8 + i;
            float v[8];
#pragma unroll
            for (int j = 0; j < 8; j++) {
                float x = acc[i][j] + bb[j];
                v[j] = (MODE == 3) ? (1.0f / (1.0f + __expf(-x))) : x;
            }
            float* p = dst + (size_t)t*CC + n0;
            *(float4*)(p)   = make_float4(v[0], v[1], v[2], v[3]);
            *(float4*)(p+4) = make_float4(v[4], v[5], v[6], v[7]);
        }
    }
}

// Attention: one block = 128 q-rows of one (s,h); thread owns one full q-row.
// Online (flash) softmax over K in tiles of 32. K/V tiles staged in smem.
#define KT 32

__global__ void __launch_bounds__(128) attn_kernel(const float* __restrict__ bias1,
                                                   const float* __restrict__ bias2)
{
    __shared__ float Ks[KT][DD];
    __shared__ float Vs[KT][DD];

    const int tid = threadIdx.x;
    const int qt  = blockIdx.x;           // 0..1
    const int h   = blockIdx.y;           // 0..3
    const int s   = blockIdx.z;           // 0..255
    const int r   = qt * 128 + tid;       // q row (j)

    const size_t headBase = ((size_t)s*HH + h) * SS * DD;

    float q[DD];
#pragma unroll
    for (int d4 = 0; d4 < DD; d4 += 4) {
        float4 v = *(const float4*)(g_Q + headBase + (size_t)r*DD + d4);
        q[d4+0]=v.x; q[d4+1]=v.y; q[d4+2]=v.z; q[d4+3]=v.w;
    }

    float o[DD];
#pragma unroll
    for (int d = 0; d < DD; d++) o[d] = 0.f;
    float mrun = -1e30f;
    float lrun = 0.f;

    const float* b1 = bias1 + ((size_t)h*SS + r) * SS;   // bias1[1,1,h,q,k]
    const float* b2 = bias2 + (size_t)s*SS;              // bias2[1,s,1,1,k]

    for (int k0 = 0; k0 < SS; k0 += KT) {
        {   // cooperative K/V tile load: KT*DD = 1024 floats each = 256 float4
            const float4* kp = (const float4*)(g_K + headBase + (size_t)k0*DD);
            const float4* vp = (const float4*)(g_V + headBase + (size_t)k0*DD);
            float4* ks4 = (float4*)&Ks[0][0];
            float4* vs4 = (float4*)&Vs[0][0];
            ks4[tid]       = kp[tid];
            ks4[tid + 128] = kp[tid + 128];
            vs4[tid]       = vp[tid];
            vs4[tid + 128] = vp[tid + 128];
        }
        __syncthreads();

        float sc[KT];
        float tmax = mrun;
#pragma unroll
        for (int kk = 0; kk < KT; kk++) {
            float a0 = 0.f, a1 = 0.f, a2 = 0.f, a3 = 0.f;
#pragma unroll
            for (int d4 = 0; d4 < DD; d4 += 4) {
                float4 kv = *(const float4*)&Ks[kk][d4];
                a0 = fmaf(q[d4+0], kv.x, a0);
                a1 = fmaf(q[d4+1], kv.y, a1);
                a2 = fmaf(q[d4+2], kv.z, a2);
                a3 = fmaf(q[d4+3], kv.w, a3);
            }
            float v = (a0 + a1) + (a2 + a3) + b1[k0 + kk] + b2[k0 + kk];
            sc[kk] = v;
            tmax = fmaxf(tmax, v);
        }

        float scale = __expf(mrun - tmax);
        mrun = tmax;
        lrun *= scale;
#pragma unroll
        for (int d = 0; d < DD; d++) o[d] *= scale;

#pragma unroll
        for (int kk = 0; kk < KT; kk++) {
            float p = __expf(sc[kk] - mrun);
            lrun += p;
#pragma unroll
            for (int d4 = 0; d4 < DD; d4 += 4) {
                float4 vv = *(const float4*)&Vs[kk][d4];
                o[d4+0] = fmaf(p, vv.x, o[d4+0]);
                o[d4+1] = fmaf(p, vv.y, o[d4+1]);
                o[d4+2] = fmaf(p, vv.z, o[d4+2]);
                o[d4+3] = fmaf(p, vv.w, o[d4+3]);
            }
        }
        __syncthreads();
    }

    const float inv = 1.0f / lrun;
    const size_t t = (size_t)s*SS + r;
    float* po = g_O + t*CC + h*DD;
    const float* pg = g_G + t*CC + h*DD;
#pragma unroll
    for (int d4 = 0; d4 < DD; d4 += 4) {
        float4 gv = *(const float4*)(pg + d4);
        float4 ov;
        ov.x = o[d4+0] * inv * gv.x;
        ov.y = o[d4+1] * inv * gv.y;
        ov.z = o[d4+2] * inv * gv.z;
        ov.w = o[d4+3] * inv * gv.w;
        *(float4*)(po + d4) = ov;
    }
}

extern "C" void kernel_launch(void* const* d_in, const int* in_sizes, int n_in,
                              void* d_out, int out_size)
{
    const float* q_x   = (const float*)d_in[0];
    const float* kv_x  = (const float*)d_in[1];
    const float* bias1 = (const float*)d_in[2];
    const float* bias2 = (const float*)d_in[3];
    const float* wq    = (const float*)d_in[4];
    const float* wk    = (const float*)d_in[5];
    const float* wv    = (const float*)d_in[6];
    const float* wg    = (const float*)d_in[7];
    const float* bg    = (const float*)d_in[8];
    const float* wo    = (const float*)d_in[9];
    const float* bo    = (const float*)d_in[10];
    float* out = (float*)d_out;

    dim3 gb(TT / 128);  // 512 blocks

    gemm128<0><<<gb, 256>>>(q_x,  wq, nullptr, nullptr);  // Q
    gemm128<1><<<gb, 256>>>(kv_x, wk, nullptr, nullptr);  // K
    gemm128<2><<<gb, 256>>>(kv_x, wv, nullptr, nullptr);  // V
    gemm128<3><<<gb, 256>>>(q_x,  wg, bg,      nullptr);  // gate (sigmoid)
    attn_kernel<<<dim3(2, HH, SS), 128>>>(bias1, bias2);  // attention + gating
    gemm128<4><<<gb, 256>>>(nullptr, wo, bo,   out);      // output projection
}

// round 3
// speedup vs baseline: 1.5531x; 1.5531x over previous
#include <cuda_runtime.h>
#include <cuda_bf16.h>

#define SS 256
#define CC 128
#define HH 4
#define DD 32
#define TT (SS*SS)

typedef unsigned int u32;

// ---------------- global scratch (no allocations allowed) ----------------
#define NQ (SS*HH*SS*DD)   // 8,388,608
__device__ __nv_bfloat16 g_Qh[NQ], g_Ql[NQ];
__device__ __nv_bfloat16 g_Kh[NQ], g_Kl[NQ];
__device__ __nv_bfloat16 g_Vh[NQ], g_Vl[NQ];
__device__ float         g_G [(size_t)TT*CC];
__device__ __nv_bfloat16 g_Oh[(size_t)TT*CC], g_Ol[(size_t)TT*CC];
__device__ __nv_bfloat16 g_Wqg_h[2*CC*CC], g_Wqg_l[2*CC*CC];
__device__ __nv_bfloat16 g_Wkv_h[2*CC*CC], g_Wkv_l[2*CC*CC];
__device__ __nv_bfloat16 g_Wo_h [CC*CC],   g_Wo_l [CC*CC];

__device__ __forceinline__ void split2(float v, __nv_bfloat16& h, __nv_bfloat16& l) {
    h = __float2bfloat16(v);
    l = __float2bfloat16(v - __bfloat162float(h));
}

__device__ __forceinline__ void mma_bf16(float* d, const u32* a, const u32* b) {
    asm volatile(
      "mma.sync.aligned.m16n8k16.row.col.f32.bf16.bf16.f32 "
      "{%0,%1,%2,%3}, {%4,%5,%6,%7}, {%8,%9}, {%0,%1,%2,%3};\n"
      : "+f"(d[0]), "+f"(d[1]), "+f"(d[2]), "+f"(d[3])
      : "r"(a[0]), "r"(a[1]), "r"(a[2]), "r"(a[3]), "r"(b[0]), "r"(b[1]));
}

// ---------------- weight prep: fp32 -> split bf16, stacked ----------------
__global__ void prep_w(const float* __restrict__ wq, const float* __restrict__ wk,
                       const float* __restrict__ wv, const float* __restrict__ wg,
                       const float* __restrict__ wo) {
    int i = blockIdx.x * blockDim.x + threadIdx.x;
    if (i >= CC*CC) return;
    split2(wq[i], g_Wqg_h[i],          g_Wqg_l[i]);
    split2(wg[i], g_Wqg_h[CC*CC + i],  g_Wqg_l[CC*CC + i]);
    split2(wk[i], g_Wkv_h[i],          g_Wkv_l[i]);
    split2(wv[i], g_Wkv_h[CC*CC + i],  g_Wkv_l[CC*CC + i]);
    split2(wo[i], g_Wo_h[i],           g_Wo_l[i]);
}

// ---------------- projection GEMM (bf16 3x-split, mma.sync) ----------------
// MODE 0: X=q_x,  W=[Wq;Wg]: y0 half -> Q split head layout (scaled), y1 half -> sigmoid gate
// MODE 1: X=kv_x, W=[Wk;Wv]: y0 -> K split head layout, y1 -> V split head layout
// MODE 2: A=g_Oh/g_Ol (bf16), W=Wo: out = y + bo (fp32)
#define AST 72           // smem K-stride (64 + 8 pad)
#define PROJ_SMEM (4*128*AST*2)

template<int MODE>
__global__ void __launch_bounds__(256, 2) proj_kernel(const float* __restrict__ X,
                                                      const float* __restrict__ bias,
                                                      float* __restrict__ outp)
{
    extern __shared__ __nv_bfloat16 sm[];
    __nv_bfloat16* Ah = sm;
    __nv_bfloat16* Al = sm + 128*AST;
    __nv_bfloat16* Bh = sm + 2*128*AST;
    __nv_bfloat16* Bl = sm + 3*128*AST;

    const int tid = threadIdx.x;
    const int lane = tid & 31;
    const int w = tid >> 5;
    const int g = lane >> 2;
    const int tg = lane & 3;
    const int wm = w & 3;     // M offset 32*wm
    const int wn = w >> 2;    // N offset 64*wn
    const int m0 = blockIdx.x * 128;
    const int n0 = blockIdx.y * 128;

    const __nv_bfloat16 *Wh, *Wl;
    if (MODE == 0)      { Wh = g_Wqg_h; Wl = g_Wqg_l; }
    else if (MODE == 1) { Wh = g_Wkv_h; Wl = g_Wkv_l; }
    else                { Wh = g_Wo_h;  Wl = g_Wo_l;  }

    float acc[2][8][4];
#pragma unroll
    for (int a = 0; a < 2; a++)
#pragma unroll
        for (int b = 0; b < 8; b++)
#pragma unroll
            for (int c = 0; c < 4; c++) acc[a][b][c] = 0.f;

    for (int ks = 0; ks < 2; ks++) {
        const int kbase = ks * 64;
        // --- load A tile (128 x 64) ---
        if (MODE < 2) {
#pragma unroll
            for (int i = 0; i < 8; i++) {
                int lin = tid + 256*i;            // float4 units
                int r = lin >> 4;
                int c = (lin & 15) * 4;
                float4 xv = *(const float4*)(X + (size_t)(m0+r)*CC + kbase + c);
                split2(xv.x, Ah[r*AST+c+0], Al[r*AST+c+0]);
                split2(xv.y, Ah[r*AST+c+1], Al[r*AST+c+1]);
                split2(xv.z, Ah[r*AST+c+2], Al[r*AST+c+2]);
                split2(xv.w, Ah[r*AST+c+3], Al[r*AST+c+3]);
            }
        } else {
#pragma unroll
            for (int i = 0; i < 16; i++) {
                int lin = tid + 256*i;            // u32 units
                int r = lin >> 5;
                int c = (lin & 31) * 2;
                *(u32*)&Ah[r*AST+c] = *(const u32*)(g_Oh + (size_t)(m0+r)*CC + kbase + c);
                *(u32*)&Al[r*AST+c] = *(const u32*)(g_Ol + (size_t)(m0+r)*CC + kbase + c);
            }
        }
        // --- load B tile (weights, [n][k] row-major) ---
#pragma unroll
        for (int i = 0; i < 16; i++) {
            int lin = tid + 256*i;
            int r = lin >> 5;
            int c = (lin & 31) * 2;
            *(u32*)&Bh[r*AST+c] = *(const u32*)(Wh + (size_t)(n0+r)*CC + kbase + c);
            *(u32*)&Bl[r*AST+c] = *(const u32*)(Wl + (size_t)(n0+r)*CC + kbase + c);
        }
        __syncthreads();

#pragma unroll
        for (int k16 = 0; k16 < 4; k16++) {
            const int kk = k16*16 + tg*2;
            u32 ah[2][4], al[2][4];
#pragma unroll
            for (int mt = 0; mt < 2; mt++) {
                int row = wm*32 + mt*16 + g;
                ah[mt][0] = *(u32*)&Ah[ row   *AST + kk];
                ah[mt][1] = *(u32*)&Ah[(row+8)*AST + kk];
                ah[mt][2] = *(u32*)&Ah[ row   *AST + kk + 8];
                ah[mt][3] = *(u32*)&Ah[(row+8)*AST + kk + 8];
                al[mt][0] = *(u32*)&Al[ row   *AST + kk];
                al[mt][1] = *(u32*)&Al[(row+8)*AST + kk];
                al[mt][2] = *(u32*)&Al[ row   *AST + kk + 8];
                al[mt][3] = *(u32*)&Al[(row+8)*AST + kk + 8];
            }
#pragma unroll
            for (int nt = 0; nt < 8; nt++) {
                int n = wn*64 + nt*8 + g;
                u32 bh[2], bl[2];
                bh[0] = *(u32*)&Bh[n*AST + kk];
                bh[1] = *(u32*)&Bh[n*AST + kk + 8];
                bl[0] = *(u32*)&Bl[n*AST + kk];
                bl[1] = *(u32*)&Bl[n*AST + kk + 8];
#pragma unroll
                for (int mt = 0; mt < 2; mt++) {
                    mma_bf16(acc[mt][nt], ah[mt], bh);
                    mma_bf16(acc[mt][nt], ah[mt], bl);
                    mma_bf16(acc[mt][nt], al[mt], bh);
                }
            }
        }
        __syncthreads();
    }

    // --- epilogue ---
#pragma unroll
    for (int mt = 0; mt < 2; mt++) {
#pragma unroll
        for (int nt = 0; nt < 8; nt++) {
#pragma unroll
            for (int rr = 0; rr < 2; rr++) {
                int m   = m0 + wm*32 + mt*16 + g + rr*8;
                int col = wn*64 + nt*8 + tg*2;        // 0..127 within N-block
                float y0 = acc[mt][nt][rr*2+0];
                float y1 = acc[mt][nt][rr*2+1];
                if (MODE == 2) {
                    float2 o; o.x = y0 + bias[col]; o.y = y1 + bias[col+1];
                    *(float2*)(outp + (size_t)m*CC + col) = o;
                } else if (blockIdx.y == 0) {
                    if (MODE == 0) { y0 *= 0.17677669529663687f; y1 *= 0.17677669529663687f; }
                    int hh = col >> 5, d = col & 31;
                    int si = m >> 8,  j = m & 255;
                    size_t idx = (((size_t)si*HH + hh)*SS + j)*DD + d;
                    __nv_bfloat162 vh, vl;
                    split2(y0, vh.x, vl.x);
                    split2(y1, vh.y, vl.y);
                    if (MODE == 0) { *(__nv_bfloat162*)&g_Qh[idx] = vh; *(__nv_bfloat162*)&g_Ql[idx] = vl; }
                    else           { *(__nv_bfloat162*)&g_Kh[idx] = vh; *(__nv_bfloat162*)&g_Kl[idx] = vl; }
                } else {
                    if (MODE == 0) {
                        float s0 = 1.f/(1.f + __expf(-(y0 + bias[col])));
                        float s1 = 1.f/(1.f + __expf(-(y1 + bias[col+1])));
                        *(float2*)(g_G + (size_t)m*CC + col) = make_float2(s0, s1);
                    } else {
                        int hh = col >> 5, d = col & 31;
                        int si = m >> 8,  j = m & 255;
                        size_t idx = (((size_t)si*HH + hh)*SS + j)*DD + d;
                        __nv_bfloat162 vh, vl;
                        split2(y0, vh.x, vl.x);
                        split2(y1, vh.y, vl.y);
                        *(__nv_bfloat162*)&g_Vh[idx] = vh;
                        *(__nv_bfloat162*)&g_Vl[idx] = vl;
                    }
                }
            }
        }
    }
}

// ---------------- attention (per CTA: 64 q rows of one (s,h)) ----------------
#define QST 40
#define KST 40
#define VST 264
#define SST 260
#define ATTN_SMEM (2*(2*64*QST + 2*256*KST + 2*32*VST) + 64*SST*4)  // 151552

__global__ void __launch_bounds__(256) attn_kernel(const float* __restrict__ bias1,
                                                   const float* __restrict__ bias2)
{
    extern __shared__ char smraw[];
    __nv_bfloat16* Qsh = (__nv_bfloat16*)smraw;          // [64][QST]
    __nv_bfloat16* Qsl = Qsh + 64*QST;
    __nv_bfloat16* Ksh = Qsl + 64*QST;                   // [256][KST]
    __nv_bfloat16* Ksl = Ksh + 256*KST;
    __nv_bfloat16* Vth = Ksl + 256*KST;                  // [32][VST] transposed
    __nv_bfloat16* Vtl = Vth + 32*VST;
    float*         Sb  = (float*)(Vtl + 32*VST);         // [64][SST]
    __shared__ float rowsum[64];

    const int tid = threadIdx.x, lane = tid & 31, w = tid >> 5;
    const int g = lane >> 2, tg = lane & 3;
    const int qblk = blockIdx.x, h = blockIdx.y, s = blockIdx.z;
    const size_t headBase = ((size_t)s*HH + h) * SS * DD;

    // ---- stage Q (64x32), K (256x32), V transposed (32x256), hi+lo ----
    // NOTE: one row = 32 bf16 = 16 u32 (the round-2 bug was copying only 8).
    if (tid < 64) {
        const u32* srcH = (const u32*)(g_Qh + headBase + (size_t)(qblk*64 + tid)*DD);
        const u32* srcL = (const u32*)(g_Ql + headBase + (size_t)(qblk*64 + tid)*DD);
        u32* dH = (u32*)&Qsh[tid*QST];
        u32* dL = (u32*)&Qsl[tid*QST];
#pragma unroll
        for (int j = 0; j < 16; j++) { dH[j] = srcH[j]; dL[j] = srcL[j]; }
    }
    {
        const u32* srcH = (const u32*)(g_Kh + headBase + (size_t)tid*DD);
        const u32* srcL = (const u32*)(g_Kl + headBase + (size_t)tid*DD);
        u32* dH = (u32*)&Ksh[tid*KST];
        u32* dL = (u32*)&Ksl[tid*KST];
#pragma unroll
        for (int j = 0; j < 16; j++) { dH[j] = srcH[j]; dL[j] = srcL[j]; }
    }
    {
        const u32* srcH = (const u32*)(g_Vh + headBase + (size_t)tid*DD);
        const u32* srcL = (const u32*)(g_Vl + headBase + (size_t)tid*DD);
#pragma unroll
        for (int j = 0; j < 16; j++) {
            u32 wv = srcH[j];
            __nv_bfloat162 p = *(__nv_bfloat162*)&wv;
            Vth[(2*j  )*VST + tid] = p.x;
            Vth[(2*j+1)*VST + tid] = p.y;
            wv = srcL[j];
            p = *(__nv_bfloat162*)&wv;
            Vtl[(2*j  )*VST + tid] = p.x;
            Vtl[(2*j+1)*VST + tid] = p.y;
        }
    }
    __syncthreads();

    // ---- QK^T: warp tile 16(M) x 128(N) ----
    {
        const int wm = w & 3, wn = w >> 2;
        float acc[16][4];
#pragma unroll
        for (int a = 0; a < 16; a++)
#pragma unroll
            for (int b = 0; b < 4; b++) acc[a][b] = 0.f;

#pragma unroll
        for (int k16 = 0; k16 < 2; k16++) {
            const int kk = k16*16 + tg*2;
            const int row = wm*16 + g;
            u32 ah[4], al[4];
            ah[0] = *(u32*)&Qsh[ row   *QST + kk];
            ah[1] = *(u32*)&Qsh[(row+8)*QST + kk];
            ah[2] = *(u32*)&Qsh[ row   *QST + kk + 8];
            ah[3] = *(u32*)&Qsh[(row+8)*QST + kk + 8];
            al[0] = *(u32*)&Qsl[ row   *QST + kk];
            al[1] = *(u32*)&Qsl[(row+8)*QST + kk];
            al[2] = *(u32*)&Qsl[ row   *QST + kk + 8];
            al[3] = *(u32*)&Qsl[(row+8)*QST + kk + 8];
#pragma unroll
            for (int nt = 0; nt < 16; nt++) {
                int n = wn*128 + nt*8 + g;
                u32 bh[2], bl[2];
                bh[0] = *(u32*)&Ksh[n*KST + kk];
                bh[1] = *(u32*)&Ksh[n*KST + kk + 8];
                bl[0] = *(u32*)&Ksl[n*KST + kk];
                bl[1] = *(u32*)&Ksl[n*KST + kk + 8];
                mma_bf16(acc[nt], ah, bh);
                mma_bf16(acc[nt], ah, bl);
                mma_bf16(acc[nt], al, bh);
            }
        }
#pragma unroll
        for (int nt = 0; nt < 16; nt++) {
            int row = wm*16 + g;
            int col = wn*128 + nt*8 + tg*2;
            *(float2*)&Sb[ row   *SST + col] = make_float2(acc[nt][0], acc[nt][1]);
            *(float2*)&Sb[(row+8)*SST + col] = make_float2(acc[nt][2], acc[nt][3]);
        }
    }
    __syncthreads();

    // ---- bias + softmax (unnormalized), repack P as split bf16 in place ----
    {
        const int r = tid >> 2, t4 = tid & 3;
        const int q = qblk*64 + r;
        const float* b1 = bias1 + ((size_t)h*SS + q) * SS;
        const float* b2 = bias2 + (size_t)s * SS;
        float m = -1e30f;
#pragma unroll
        for (int j = 0; j < 64; j++) {
            int c = t4 + 4*j;
            float v = Sb[r*SST + c] + b1[c] + b2[c];
            Sb[r*SST + c] = v;
            m = fmaxf(m, v);
        }
        m = fmaxf(m, __shfl_xor_sync(0xffffffffu, m, 1));
        m = fmaxf(m, __shfl_xor_sync(0xffffffffu, m, 2));
        float ssum = 0.f;
#pragma unroll
        for (int j = 0; j < 64; j++) {
            int c = t4 + 4*j;
            float p = __expf(Sb[r*SST + c] - m);
            ssum += p;
            __nv_bfloat162 pk;
            split2(p, pk.x, pk.y);
            *(__nv_bfloat162*)&Sb[r*SST + c] = pk;
        }
        ssum += __shfl_xor_sync(0xffffffffu, ssum, 1);
        ssum += __shfl_xor_sync(0xffffffffu, ssum, 2);
        if (t4 == 0) rowsum[r] = ssum;
    }
    __syncthreads();

    // ---- P·V: warp tile 16(M) x 16(N), K=256 ----
    {
        const int wm = w & 3, wn = w >> 2;
        const u32* S32 = (const u32*)Sb;
        float acc[2][4];
#pragma unroll
        for (int a = 0; a < 2; a++)
#pragma unroll
            for (int b = 0; b < 4; b++) acc[a][b] = 0.f;

#pragma unroll
        for (int k16 = 0; k16 < 16; k16++) {
            const int kk = k16*16 + tg*2;
            const int row = wm*16 + g;
            u32 w0 = S32[ row   *SST + kk],     w1 = S32[ row   *SST + kk + 1];
            u32 w2 = S32[(row+8)*SST + kk],     w3 = S32[(row+8)*SST + kk + 1];
            u32 w4 = S32[ row   *SST + kk + 8], w5 = S32[ row   *SST + kk + 9];
            u32 w6 = S32[(row+8)*SST + kk + 8], w7 = S32[(row+8)*SST + kk + 9];
            u32 ah[4], al[4];
            ah[0] = __byte_perm(w0, w1, 0x5410); al[0] = __byte_perm(w0, w1, 0x7632);
            ah[1] = __byte_perm(w2, w3, 0x5410); al[1] = __byte_perm(w2, w3, 0x7632);
            ah[2] = __byte_perm(w4, w5, 0x5410); al[2] = __byte_perm(w4, w5, 0x7632);
            ah[3] = __byte_perm(w6, w7, 0x5410); al[3] = __byte_perm(w6, w7, 0x7632);
#pragma unroll
            for (int nt = 0; nt < 2; nt++) {
                int n = wn*16 + nt*8 + g;
                u32 bh[2], bl[2];
                bh[0] = *(u32*)&Vth[n*VST + kk];
                bh[1] = *(u32*)&Vth[n*VST + kk + 8];
                bl[0] = *(u32*)&Vtl[n*VST + kk];
                bl[1] = *(u32*)&Vtl[n*VST + kk + 8];
                mma_bf16(acc[nt], ah, bh);
                mma_bf16(acc[nt], ah, bl);
                mma_bf16(acc[nt], al, bh);
            }
        }

        // ---- epilogue: normalize, gate, split-bf16 write ----
#pragma unroll
        for (int nt = 0; nt < 2; nt++) {
#pragma unroll
            for (int rr = 0; rr < 2; rr++) {
                int row = wm*16 + g + rr*8;
                int t = s*SS + qblk*64 + row;
                float inv = 1.0f / rowsum[row];
                int c = wn*16 + nt*8 + tg*2;
                int col = h*DD + c;
                float2 gg = *(const float2*)(g_G + (size_t)t*CC + col);
                float o0 = acc[nt][rr*2+0] * inv * gg.x;
                float o1 = acc[nt][rr*2+1] * inv * gg.y;
                __nv_bfloat162 oh, ol;
                split2(o0, oh.x, ol.x);
                split2(o1, oh.y, ol.y);
                *(__nv_bfloat162*)&g_Oh[(size_t)t*CC + col] = oh;
                *(__nv_bfloat162*)&g_Ol[(size_t)t*CC + col] = ol;
            }
        }
    }
}

// ---------------- launch ----------------
extern "C" void kernel_launch(void* const* d_in, const int* in_sizes, int n_in,
                              void* d_out, int out_size)
{
    const float* q_x   = (const float*)d_in[0];
    const float* kv_x  = (const float*)d_in[1];
    const float* bias1 = (const float*)d_in[2];
    const float* bias2 = (const float*)d_in[3];
    const float* wq    = (const float*)d_in[4];
    const float* wk    = (const float*)d_in[5];
    const float* wv    = (const float*)d_in[6];
    const float* wg    = (const float*)d_in[7];
    const float* bg    = (const float*)d_in[8];
    const float* wo    = (const float*)d_in[9];
    const float* bo    = (const float*)d_in[10];
    float* out = (float*)d_out;

    cudaFuncSetAttribute(proj_kernel<0>, cudaFuncAttributeMaxDynamicSharedMemorySize, PROJ_SMEM);
    cudaFuncSetAttribute(proj_kernel<1>, cudaFuncAttributeMaxDynamicSharedMemorySize, PROJ_SMEM);
    cudaFuncSetAttribute(proj_kernel<2>, cudaFuncAttributeMaxDynamicSharedMemorySize, PROJ_SMEM);
    cudaFuncSetAttribute(attn_kernel,    cudaFuncAttributeMaxDynamicSharedMemorySize, ATTN_SMEM);

    prep_w<<<64, 256>>>(wq, wk, wv, wg, wo);
    proj_kernel<0><<<dim3(512, 2), 256, PROJ_SMEM>>>(q_x,  bg, nullptr);
    proj_kernel<1><<<dim3(512, 2), 256, PROJ_SMEM>>>(kv_x, nullptr, nullptr);
    attn_kernel<<<dim3(4, HH, SS), 256, ATTN_SMEM>>>(bias1, bias2);
    proj_kernel<2><<<dim3(512, 1), 256, PROJ_SMEM>>>(nullptr, bo, out);
}

// round 5
// speedup vs baseline: 2.8010x; 1.8035x over previous
#include <cuda_runtime.h>
#include <cuda_bf16.h>

#define SS 256
#define CC 128
#define HH 4
#define DD 32
#define TT (SS*SS)

typedef unsigned int u32;

// ---------------- global scratch (no allocations allowed) ----------------
#define NQ (SS*HH*SS*DD)   // 8,388,608
__device__ __nv_bfloat16 g_Qh[NQ], g_Ql[NQ];
__device__ __nv_bfloat16 g_Kh[NQ], g_Kl[NQ];
__device__ __nv_bfloat16 g_Vh[NQ], g_Vl[NQ];
__device__ float         g_G [(size_t)TT*CC];
__device__ __nv_bfloat16 g_Oh[(size_t)TT*CC], g_Ol[(size_t)TT*CC];
__device__ __nv_bfloat16 g_Wqg_h[2*CC*CC], g_Wqg_l[2*CC*CC];
__device__ __nv_bfloat16 g_Wkv_h[2*CC*CC], g_Wkv_l[2*CC*CC];
__device__ __nv_bfloat16 g_Wo_h [CC*CC],   g_Wo_l [CC*CC];

__device__ __forceinline__ void split2(float v, __nv_bfloat16& h, __nv_bfloat16& l) {
    h = __float2bfloat16(v);
    l = __float2bfloat16(v - __bfloat162float(h));
}

__device__ __forceinline__ void mma_bf16(float* d, const u32* a, const u32* b) {
    asm volatile(
      "mma.sync.aligned.m16n8k16.row.col.f32.bf16.bf16.f32 "
      "{%0,%1,%2,%3}, {%4,%5,%6,%7}, {%8,%9}, {%0,%1,%2,%3};\n"
      : "+f"(d[0]), "+f"(d[1]), "+f"(d[2]), "+f"(d[3])
      : "r"(a[0]), "r"(a[1]), "r"(a[2]), "r"(a[3]), "r"(b[0]), "r"(b[1]));
}

// ---------------- weight prep: fp32 -> split bf16, stacked ----------------
__global__ void prep_w(const float* __restrict__ wq, const float* __restrict__ wk,
                       const float* __restrict__ wv, const float* __restrict__ wg,
                       const float* __restrict__ wo) {
    int i = blockIdx.x * blockDim.x + threadIdx.x;
    if (i >= CC*CC) return;
    split2(wq[i], g_Wqg_h[i],          g_Wqg_l[i]);
    split2(wg[i], g_Wqg_h[CC*CC + i],  g_Wqg_l[CC*CC + i]);
    split2(wk[i], g_Wkv_h[i],          g_Wkv_l[i]);
    split2(wv[i], g_Wkv_h[CC*CC + i],  g_Wkv_l[CC*CC + i]);
    split2(wo[i], g_Wo_h[i],           g_Wo_l[i]);
}

// ---------------- projection GEMM (bf16 3x-split, mma.sync) ----------------
#define AST 72
#define PROJ_SMEM (4*128*AST*2)

template<int MODE>
__global__ void __launch_bounds__(256, 2) proj_kernel(const float* __restrict__ X,
                                                      const float* __restrict__ bias,
                                                      float* __restrict__ outp)
{
    extern __shared__ __nv_bfloat16 sm[];
    __nv_bfloat16* Ah = sm;
    __nv_bfloat16* Al = sm + 128*AST;
    __nv_bfloat16* Bh = sm + 2*128*AST;
    __nv_bfloat16* Bl = sm + 3*128*AST;

    const int tid = threadIdx.x;
    const int lane = tid & 31;
    const int w = tid >> 5;
    const int g = lane >> 2;
    const int tg = lane & 3;
    const int wm = w & 3;
    const int wn = w >> 2;
    const int m0 = blockIdx.x * 128;
    const int n0 = blockIdx.y * 128;

    const __nv_bfloat16 *Wh, *Wl;
    if (MODE == 0)      { Wh = g_Wqg_h; Wl = g_Wqg_l; }
    else if (MODE == 1) { Wh = g_Wkv_h; Wl = g_Wkv_l; }
    else                { Wh = g_Wo_h;  Wl = g_Wo_l;  }

    float acc[2][8][4];
#pragma unroll
    for (int a = 0; a < 2; a++)
#pragma unroll
        for (int b = 0; b < 8; b++)
#pragma unroll
            for (int c = 0; c < 4; c++) acc[a][b][c] = 0.f;

    for (int ks = 0; ks < 2; ks++) {
        const int kbase = ks * 64;
        if (MODE < 2) {
#pragma unroll
            for (int i = 0; i < 8; i++) {
                int lin = tid + 256*i;
                int r = lin >> 4;
                int c = (lin & 15) * 4;
                float4 xv = *(const float4*)(X + (size_t)(m0+r)*CC + kbase + c);
                split2(xv.x, Ah[r*AST+c+0], Al[r*AST+c+0]);
                split2(xv.y, Ah[r*AST+c+1], Al[r*AST+c+1]);
                split2(xv.z, Ah[r*AST+c+2], Al[r*AST+c+2]);
                split2(xv.w, Ah[r*AST+c+3], Al[r*AST+c+3]);
            }
        } else {
#pragma unroll
            for (int i = 0; i < 16; i++) {
                int lin = tid + 256*i;
                int r = lin >> 5;
                int c = (lin & 31) * 2;
                *(u32*)&Ah[r*AST+c] = *(const u32*)(g_Oh + (size_t)(m0+r)*CC + kbase + c);
                *(u32*)&Al[r*AST+c] = *(const u32*)(g_Ol + (size_t)(m0+r)*CC + kbase + c);
            }
        }
#pragma unroll
        for (int i = 0; i < 16; i++) {
            int lin = tid + 256*i;
            int r = lin >> 5;
            int c = (lin & 31) * 2;
            *(u32*)&Bh[r*AST+c] = *(const u32*)(Wh + (size_t)(n0+r)*CC + kbase + c);
            *(u32*)&Bl[r*AST+c] = *(const u32*)(Wl + (size_t)(n0+r)*CC + kbase + c);
        }
        __syncthreads();

#pragma unroll
        for (int k16 = 0; k16 < 4; k16++) {
            const int kk = k16*16 + tg*2;
            u32 ah[2][4], al[2][4];
#pragma unroll
            for (int mt = 0; mt < 2; mt++) {
                int row = wm*32 + mt*16 + g;
                ah[mt][0] = *(u32*)&Ah[ row   *AST + kk];
                ah[mt][1] = *(u32*)&Ah[(row+8)*AST + kk];
                ah[mt][2] = *(u32*)&Ah[ row   *AST + kk + 8];
                ah[mt][3] = *(u32*)&Ah[(row+8)*AST + kk + 8];
                al[mt][0] = *(u32*)&Al[ row   *AST + kk];
                al[mt][1] = *(u32*)&Al[(row+8)*AST + kk];
                al[mt][2] = *(u32*)&Al[ row   *AST + kk + 8];
                al[mt][3] = *(u32*)&Al[(row+8)*AST + kk + 8];
            }
#pragma unroll
            for (int nt = 0; nt < 8; nt++) {
                int n = wn*64 + nt*8 + g;
                u32 bh[2], bl[2];
                bh[0] = *(u32*)&Bh[n*AST + kk];
                bh[1] = *(u32*)&Bh[n*AST + kk + 8];
                bl[0] = *(u32*)&Bl[n*AST + kk];
                bl[1] = *(u32*)&Bl[n*AST + kk + 8];
#pragma unroll
                for (int mt = 0; mt < 2; mt++) {
                    mma_bf16(acc[mt][nt], ah[mt], bh);
                    mma_bf16(acc[mt][nt], ah[mt], bl);
                    mma_bf16(acc[mt][nt], al[mt], bh);
                }
            }
        }
        __syncthreads();
    }

#pragma unroll
    for (int mt = 0; mt < 2; mt++) {
#pragma unroll
        for (int nt = 0; nt < 8; nt++) {
#pragma unroll
            for (int rr = 0; rr < 2; rr++) {
                int m   = m0 + wm*32 + mt*16 + g + rr*8;
                int col = wn*64 + nt*8 + tg*2;
                float y0 = acc[mt][nt][rr*2+0];
                float y1 = acc[mt][nt][rr*2+1];
                if (MODE == 2) {
                    float2 o; o.x = y0 + bias[col]; o.y = y1 + bias[col+1];
                    *(float2*)(outp + (size_t)m*CC + col) = o;
                } else if (blockIdx.y == 0) {
                    if (MODE == 0) { y0 *= 0.17677669529663687f; y1 *= 0.17677669529663687f; }
                    int hh = col >> 5, d = col & 31;
                    int si = m >> 8,  j = m & 255;
                    size_t idx = (((size_t)si*HH + hh)*SS + j)*DD + d;
                    __nv_bfloat162 vh, vl;
                    split2(y0, vh.x, vl.x);
                    split2(y1, vh.y, vl.y);
                    if (MODE == 0) { *(__nv_bfloat162*)&g_Qh[idx] = vh; *(__nv_bfloat162*)&g_Ql[idx] = vl; }
                    else           { *(__nv_bfloat162*)&g_Kh[idx] = vh; *(__nv_bfloat162*)&g_Kl[idx] = vl; }
                } else {
                    if (MODE == 0) {
                        float s0 = 1.f/(1.f + __expf(-(y0 + bias[col])));
                        float s1 = 1.f/(1.f + __expf(-(y1 + bias[col+1])));
                        *(float2*)(g_G + (size_t)m*CC + col) = make_float2(s0, s1);
                    } else {
                        int hh = col >> 5, d = col & 31;
                        int si = m >> 8,  j = m & 255;
                        size_t idx = (((size_t)si*HH + hh)*SS + j)*DD + d;
                        __nv_bfloat162 vh, vl;
                        split2(y0, vh.x, vl.x);
                        split2(y1, vh.y, vl.y);
                        *(__nv_bfloat162*)&g_Vh[idx] = vh;
                        *(__nv_bfloat162*)&g_Vl[idx] = vl;
                    }
                }
            }
        }
    }
}

// ---------------- attention v2: register-resident FA2 style ----------------
// CTA = one (s,h): 512 threads / 16 warps, warp owns 16 q-rows x all 256 k.
// K in two 128-halves with online softmax; P stays in registers (C-frag -> A-frag),
// exp/pack/PV fused per k16 chunk to bound live registers.
#define KST 40
#define VST 264
#define ATTN_SMEM (2*256*KST*2 + 2*32*VST*2 + 256*4)   // 75776 B

__global__ void __launch_bounds__(512, 1) attn_kernel(const float* __restrict__ bias1,
                                                      const float* __restrict__ bias2)
{
    extern __shared__ char smraw[];
    __nv_bfloat16* Ksh = (__nv_bfloat16*)smraw;   // [256][KST]
    __nv_bfloat16* Ksl = Ksh + 256*KST;
    __nv_bfloat16* Vth = Ksl + 256*KST;           // [32][VST] (d-major, k across)
    __nv_bfloat16* Vtl = Vth + 32*VST;
    float*         b2s = (float*)(Vtl + 32*VST);  // [256]

    const int tid = threadIdx.x, lane = tid & 31, w = tid >> 5;
    const int g = lane >> 2, tg = lane & 3;
    const int h = blockIdx.x, s = blockIdx.y;
    const size_t headBase = ((size_t)s*HH + h) * SS * DD;

    // ---- stage K (coalesced uint4) ----
    {
        const uint4* sh = (const uint4*)(g_Kh + headBase);
        const uint4* sl = (const uint4*)(g_Kl + headBase);
#pragma unroll
        for (int it = 0; it < 2; it++) {
            int i = tid + it*512;                 // 0..1023 uint4
            int row = i >> 2, q4 = i & 3;
            *(uint4*)&Ksh[row*KST + q4*8] = sh[i];
            *(uint4*)&Ksl[row*KST + q4*8] = sl[i];
        }
    }
    // ---- stage V transposed: Vt[d][k] ----
    {
        int row = tid >> 1, half = tid & 1;
        const u32* sh = (const u32*)(g_Vh + headBase + (size_t)row*DD) + half*8;
        const u32* sl = (const u32*)(g_Vl + headBase + (size_t)row*DD) + half*8;
#pragma unroll
        for (int j = 0; j < 8; j++) {
            int d = (half*8 + j) * 2;
            u32 v = sh[j];
            __nv_bfloat162 p = *(__nv_bfloat162*)&v;
            Vth[ d   *VST + row] = p.x;
            Vth[(d+1)*VST + row] = p.y;
            v = sl[j];
            p = *(__nv_bfloat162*)&v;
            Vtl[ d   *VST + row] = p.x;
            Vtl[(d+1)*VST + row] = p.y;
        }
    }
    if (tid < 256) b2s[tid] = bias2[(size_t)s*SS + tid];
    __syncthreads();

    // ---- Q fragments (direct from gmem, 16 q-rows per warp) ----
    const int q0 = w * 16;
    u32 qh[2][4], ql[2][4];
    {
        const u32* srcH = (const u32*)(g_Qh + headBase);
        const u32* srcL = (const u32*)(g_Ql + headBase);
        int r0 = q0 + g, r1 = q0 + g + 8;
#pragma unroll
        for (int sl2 = 0; sl2 < 2; sl2++) {
            int kc = sl2*8 + tg;                  // u32 col
            qh[sl2][0] = srcH[r0*16 + kc];
            qh[sl2][1] = srcH[r1*16 + kc];
            qh[sl2][2] = srcH[r0*16 + kc + 4];
            qh[sl2][3] = srcH[r1*16 + kc + 4];
            ql[sl2][0] = srcL[r0*16 + kc];
            ql[sl2][1] = srcL[r1*16 + kc];
            ql[sl2][2] = srcL[r0*16 + kc + 4];
            ql[sl2][3] = srcL[r1*16 + kc + 4];
        }
    }

    const float* b1a_p = bias1 + ((size_t)h*SS + q0 + g) * SS;
    const float* b1b_p = b1a_p + 8*SS;

    float acc[4][4];
#pragma unroll
    for (int a = 0; a < 4; a++)
#pragma unroll
        for (int b = 0; b < 4; b++) acc[a][b] = 0.f;
    float m_a = -1e30f, m_b = -1e30f, l_a = 0.f, l_b = 0.f;

#pragma unroll
    for (int kh = 0; kh < 2; kh++) {
        // ---- QK^T for this 128-key half ----
        float sc[16][4];
#pragma unroll
        for (int nt = 0; nt < 16; nt++) {
#pragma unroll
            for (int c = 0; c < 4; c++) sc[nt][c] = 0.f;
        }
#pragma unroll
        for (int nt = 0; nt < 16; nt++) {
            int n = kh*128 + nt*8 + g;
#pragma unroll
            for (int sl2 = 0; sl2 < 2; sl2++) {
                int kk = sl2*16 + tg*2;
                u32 bh[2], bl[2];
                bh[0] = *(u32*)&Ksh[n*KST + kk];
                bh[1] = *(u32*)&Ksh[n*KST + kk + 8];
                bl[0] = *(u32*)&Ksl[n*KST + kk];
                bl[1] = *(u32*)&Ksl[n*KST + kk + 8];
                mma_bf16(sc[nt], qh[sl2], bh);
                mma_bf16(sc[nt], qh[sl2], bl);
                mma_bf16(sc[nt], ql[sl2], bh);
            }
        }
        // ---- bias add + per-row max (rows g and g+8 separate) ----
        float ta = -1e30f, tb = -1e30f;
#pragma unroll
        for (int nt = 0; nt < 16; nt++) {
            int c = kh*128 + nt*8 + tg*2;
            float2 ba = *(const float2*)(b1a_p + c);
            float2 bb = *(const float2*)(b1b_p + c);
            float2 b2v = *(float2*)&b2s[c];
            sc[nt][0] += ba.x + b2v.x;
            sc[nt][1] += ba.y + b2v.y;
            sc[nt][2] += bb.x + b2v.x;
            sc[nt][3] += bb.y + b2v.y;
            ta = fmaxf(ta, fmaxf(sc[nt][0], sc[nt][1]));
            tb = fmaxf(tb, fmaxf(sc[nt][2], sc[nt][3]));
        }
        ta = fmaxf(ta, __shfl_xor_sync(0xffffffffu, ta, 1));
        ta = fmaxf(ta, __shfl_xor_sync(0xffffffffu, ta, 2));
        tb = fmaxf(tb, __shfl_xor_sync(0xffffffffu, tb, 1));
        tb = fmaxf(tb, __shfl_xor_sync(0xffffffffu, tb, 2));

        float mna = fmaxf(m_a, ta), mnb = fmaxf(m_b, tb);
        float sca = __expf(m_a - mna), scb = __expf(m_b - mnb);
        m_a = mna; m_b = mnb;
        l_a *= sca; l_b *= scb;
#pragma unroll
        for (int nd = 0; nd < 4; nd++) {
            acc[nd][0] *= sca; acc[nd][1] *= sca;
            acc[nd][2] *= scb; acc[nd][3] *= scb;
        }

        // ---- fused exp + pack + P·V per k16 chunk (bounds live regs) ----
#pragma unroll
        for (int s8 = 0; s8 < 8; s8++) {
            u32 ah[4], al[4];
#pragma unroll
            for (int half = 0; half < 2; half++) {
                int nt = 2*s8 + half;
                float p0 = __expf(sc[nt][0] - m_a);
                float p1 = __expf(sc[nt][1] - m_a);
                float p2 = __expf(sc[nt][2] - m_b);
                float p3 = __expf(sc[nt][3] - m_b);
                l_a += p0 + p1;
                l_b += p2 + p3;
                __nv_bfloat162 hv, lv;
                split2(p0, hv.x, lv.x); split2(p1, hv.y, lv.y);
                ah[half*2]     = *(u32*)&hv;  al[half*2]     = *(u32*)&lv;
                split2(p2, hv.x, lv.x); split2(p3, hv.y, lv.y);
                ah[half*2 + 1] = *(u32*)&hv;  al[half*2 + 1] = *(u32*)&lv;
            }
            int kkg = kh*128 + s8*16 + tg*2;
#pragma unroll
            for (int nd = 0; nd < 4; nd++) {
                int n = nd*8 + g;
                u32 bh[2], bl[2];
                bh[0] = *(u32*)&Vth[n*VST + kkg];
                bh[1] = *(u32*)&Vth[n*VST + kkg + 8];
                bl[0] = *(u32*)&Vtl[n*VST + kkg];
                bl[1] = *(u32*)&Vtl[n*VST + kkg + 8];
                mma_bf16(acc[nd], ah, bh);
                mma_bf16(acc[nd], ah, bl);
                mma_bf16(acc[nd], al, bh);
            }
        }
    }

    // ---- reduce row-sums across the 4 tg lanes sharing each row ----
    l_a += __shfl_xor_sync(0xffffffffu, l_a, 1);
    l_a += __shfl_xor_sync(0xffffffffu, l_a, 2);
    l_b += __shfl_xor_sync(0xffffffffu, l_b, 1);
    l_b += __shfl_xor_sync(0xffffffffu, l_b, 2);

    // ---- epilogue: normalize, gate, split-bf16 store ----
    const float inva = 1.0f / l_a;
    const float invb = 1.0f / l_b;
    const int ta_t = s*SS + q0 + g;
    const int tb_t = ta_t + 8;
#pragma unroll
    for (int nd = 0; nd < 4; nd++) {
        int col = h*DD + nd*8 + tg*2;
        float2 ga = *(const float2*)(g_G + (size_t)ta_t*CC + col);
        float2 gb = *(const float2*)(g_G + (size_t)tb_t*CC + col);
        float o0 = acc[nd][0] * inva * ga.x;
        float o1 = acc[nd][1] * inva * ga.y;
        float o2 = acc[nd][2] * invb * gb.x;
        float o3 = acc[nd][3] * invb * gb.y;
        __nv_bfloat162 oh, ol;
        split2(o0, oh.x, ol.x); split2(o1, oh.y, ol.y);
        *(__nv_bfloat162*)&g_Oh[(size_t)ta_t*CC + col] = oh;
        *(__nv_bfloat162*)&g_Ol[(size_t)ta_t*CC + col] = ol;
        split2(o2, oh.x, ol.x); split2(o3, oh.y, ol.y);
        *(__nv_bfloat162*)&g_Oh[(size_t)tb_t*CC + col] = oh;
        *(__nv_bfloat162*)&g_Ol[(size_t)tb_t*CC + col] = ol;
    }
}

// ---------------- launch ----------------
extern "C" void kernel_launch(void* const* d_in, const int* in_sizes, int n_in,
                              void* d_out, int out_size)
{
    const float* q_x   = (const float*)d_in[0];
    const float* kv_x  = (const float*)d_in[1];
    const float* bias1 = (const float*)d_in[2];
    const float* bias2 = (const float*)d_in[3];
    const float* bg    = (const float*)d_in[8];
    const float* bo    = (const float*)d_in[10];
    float* out = (float*)d_out;

    cudaFuncSetAttribute(proj_kernel<0>, cudaFuncAttributeMaxDynamicSharedMemorySize, PROJ_SMEM);
    cudaFuncSetAttribute(proj_kernel<1>, cudaFuncAttributeMaxDynamicSharedMemorySize, PROJ_SMEM);
    cudaFuncSetAttribute(proj_kernel<2>, cudaFuncAttributeMaxDynamicSharedMemorySize, PROJ_SMEM);
    cudaFuncSetAttribute(attn_kernel,    cudaFuncAttributeMaxDynamicSharedMemorySize, ATTN_SMEM);

    prep_w<<<64, 256>>>((const float*)d_in[4], (const float*)d_in[5],
                        (const float*)d_in[6], (const float*)d_in[7],
                        (const float*)d_in[9]);
    proj_kernel<0><<<dim3(512, 2), 256, PROJ_SMEM>>>(q_x,  bg, nullptr);
    proj_kernel<1><<<dim3(512, 2), 256, PROJ_SMEM>>>(kv_x, nullptr, nullptr);
    attn_kernel<<<dim3(HH, SS), 512, ATTN_SMEM>>>(bias1, bias2);
    proj_kernel<2><<<dim3(512, 1), 256, PROJ_SMEM>>>(nullptr, bo, out);
}